// round 17
// baseline (speedup 1.0000x reference)
#include <cuda_runtime.h>
#include <cstdint>

#define NB    32
#define CC    256
#define HH    56
#define WWD   56
#define HWH   (HH*WWD)        /* 3136  */
#define NPIX  (NB*HWH)        /* 100352 */
#define KKT   2304            /* 256*9 */
#define EPSV  1e-5f
#define GRIDX (NPIX/64)       /* 1568 */
#define PW    58              /* padded width  */
#define PIMG  (PW*PW)         /* 3364 padded px per image */

// ---------------- static device scratch (no allocations allowed) ----------------
// Padded activation bits: zero guard ring per image (globals are zero-init;
// guards never written). Guard taps contribute popc(w), removed exactly in the
// epilogue via per-(oc,tap) corrections.
__device__ uint32_t g_abits[NB * PIMG * 8];   // 3.44 MB
__device__ uint32_t g_wbits[CC * 72];         // packed weight bits, 72 words / oc
__device__ int      g_corr[CC * 9];           // 256 - 2*popc(weights of tap)
__device__ float    g_alpha[CC];
__device__ float    g_a[NPIX];                // channel mean per pixel
__device__ float    g_K[NPIX];                // 3x3 box of g_a / 9
__device__ float    g_s1[CC], g_h1[CC];       // bn1 scale / shift
__device__ float    g_s2[CC], g_h2[CC];       // bn2 scale / shift
__device__ float    g_p1[CC * GRIDX];         // bn2 partial sums   (1.6MB)
__device__ float    g_p2[CC * GRIDX];         // bn2 partial sumsq  (1.6MB)
__device__ float    g_r[(size_t)NPIX * CC];   // relu(conv1) fp32 (102.8 MB)

// ============== BN1 statistics: one block per channel, float4 + n-unroll =======
__global__ void bn_stats_kernel(const float* __restrict__ x,
                                const float* __restrict__ gamma,
                                const float* __restrict__ beta,
                                float* __restrict__ scale,
                                float* __restrict__ shift)
{
    const int c = blockIdx.x;
    float s = 0.f, s2 = 0.f;
    for (int n = 0; n < NB; n += 2) {
        const float4* pa = (const float4*)(x + ((size_t)n * CC + c) * HWH);
        const float4* pb = (const float4*)(x + ((size_t)(n + 1) * CC + c) * HWH);
        for (int i = threadIdx.x; i < HWH / 4; i += blockDim.x) {
            float4 va = pa[i], vb = pb[i];
            s  += (va.x + va.y) + (va.z + va.w) + (vb.x + vb.y) + (vb.z + vb.w);
            s2 += (va.x*va.x + va.y*va.y) + (va.z*va.z + va.w*va.w)
                + (vb.x*vb.x + vb.y*vb.y) + (vb.z*vb.z + vb.w*vb.w);
        }
    }
    __shared__ float sh[512], sh2[512];
    sh[threadIdx.x]  = s;
    sh2[threadIdx.x] = s2;
    __syncthreads();
    for (int o = 256; o > 0; o >>= 1) {
        if (threadIdx.x < o) {
            sh[threadIdx.x]  += sh[threadIdx.x + o];
            sh2[threadIdx.x] += sh2[threadIdx.x + o];
        }
        __syncthreads();
    }
    if (threadIdx.x == 0) {
        const float inv_n = 1.0f / (float)((size_t)NB * HWH);
        float m   = sh[0] * inv_n;
        float var = sh2[0] * inv_n - m * m;
        float sc  = gamma[c] * rsqrtf(var + EPSV);
        scale[c] = sc;
        shift[c] = beta[c] - m * sc;
    }
}

// ======== BN2 finalize from deterministic partials written by conv1 ============
__global__ void bn2_finalize_kernel(const float* __restrict__ p1,
                                    const float* __restrict__ p2,
                                    const float* __restrict__ gamma,
                                    const float* __restrict__ beta,
                                    float* __restrict__ scale,
                                    float* __restrict__ shift)
{
    const int c = blockIdx.x;
    float s = 0.f, s2 = 0.f;
    for (int i = threadIdx.x; i < GRIDX; i += 256) {
        s  += p1[c * GRIDX + i];
        s2 += p2[c * GRIDX + i];
    }
    __shared__ float sh[256], sh2[256];
    sh[threadIdx.x]  = s;
    sh2[threadIdx.x] = s2;
    __syncthreads();
    for (int o = 128; o > 0; o >>= 1) {
        if (threadIdx.x < o) {
            sh[threadIdx.x]  += sh[threadIdx.x + o];
            sh2[threadIdx.x] += sh2[threadIdx.x + o];
        }
        __syncthreads();
    }
    if (threadIdx.x == 0) {
        const float inv_n = 1.0f / (float)((size_t)NB * HWH);
        float m   = sh[0] * inv_n;
        float var = sh2[0] * inv_n - m * m;
        float sc  = gamma[c] * rsqrtf(var + EPSV);
        scale[c] = sc;
        shift[c] = beta[c] - m * sc;
    }
}

// ======= weight prep: alpha[oc] + bit pack + per-tap popcount correction =======
__global__ void wprep_kernel(const float* __restrict__ w,
                             float* __restrict__ alpha,
                             uint32_t* __restrict__ wbits,
                             int* __restrict__ corr)
{
    const int oc = blockIdx.x;
    const float* wp = w + (size_t)oc * KKT;   // [ic][ky][kx]

    float s = 0.f;
    for (int i = threadIdx.x; i < KKT; i += 256) s += fabsf(wp[i]);
    __shared__ float sh[256];
    __shared__ int   spc[72];
    sh[threadIdx.x] = s;
    __syncthreads();
    for (int o = 128; o > 0; o >>= 1) {
        if (threadIdx.x < o) sh[threadIdx.x] += sh[threadIdx.x + o];
        __syncthreads();
    }
    if (threadIdx.x == 0) alpha[oc] = sh[0] * (1.0f / (float)KKT);

    if (threadIdx.x < 72) {
        const int t  = threadIdx.x >> 3;   // tap 0..8 (ky*3+kx)
        const int wd = threadIdx.x & 7;    // word 0..7
        uint32_t bits = 0;
        #pragma unroll
        for (int b = 0; b < 32; b++) {
            int ch = wd * 32 + b;
            float v = wp[ch * 9 + t];
            bits |= (v > 0.f ? 1u : 0u) << b;
        }
        wbits[oc * 72 + t * 8 + wd] = bits;
        spc[threadIdx.x] = __popc(bits);
    }
    __syncthreads();
    if (threadIdx.x < 9) {
        int pc = 0;
        #pragma unroll
        for (int wd = 0; wd < 8; wd++) pc += spc[threadIdx.x * 8 + wd];
        corr[oc * 9 + threadIdx.x] = 256 - 2 * pc;   // guard-tap contribution
    }
}

// ====== BN apply + sign-pack (padded layout) + channel mean ====================
__global__ void bn_apply_pack_kernel(const float* __restrict__ x,
                                     const float* __restrict__ scale,
                                     const float* __restrict__ shift,
                                     uint32_t* __restrict__ abits,
                                     float* __restrict__ amean)
{
    const int lane = threadIdx.x & 31;
    const int wy   = threadIdx.x >> 5;        // channels [32wy, 32wy+32)
    const int pix  = blockIdx.x * 32 + lane;
    const int n = pix / HWH;
    const int p = pix - n * HWH;
    const int h = p / WWD;
    const int w = p - h * WWD;

    const float* base = x + ((size_t)n * CC + wy * 32) * HWH + p;
    uint32_t bits = 0;
    float s = 0.f;
    #pragma unroll
    for (int i = 0; i < 32; i++) {
        const int c = wy * 32 + i;
        float v = fmaf(base[(size_t)i * HWH], scale[c], shift[c]);
        s += v;
        bits |= (v > 0.f ? 1u : 0u) << i;
    }
    abits[((size_t)n * PIMG + (h + 1) * PW + (w + 1)) * 8 + wy] = bits;

    __shared__ float sh[8][32];
    sh[wy][lane] = s;
    __syncthreads();
    if (wy == 0) {
        float t = 0.f;
        #pragma unroll
        for (int k = 0; k < 8; k++) t += sh[k][lane];   // fixed order
        amean[pix] = t * (1.0f / 256.0f);
    }
}

// ================= 3x3 box filter / 9 with zero padding ========================
__global__ void box3_kernel(const float* __restrict__ a, float* __restrict__ K)
{
    const int idx = blockIdx.x * 256 + threadIdx.x;
    if (idx >= NPIX) return;
    const int n = idx / HWH;
    const int p = idx - n * HWH;
    const int h = p / WWD;
    const int w = p - h * WWD;
    const float* an = a + (size_t)n * HWH;
    float s = 0.f;
    #pragma unroll
    for (int dy = -1; dy <= 1; dy++) {
        int hh = h + dy;
        if (hh < 0 || hh >= HH) continue;
        #pragma unroll
        for (int dx = -1; dx <= 1; dx++) {
            int ww = w + dx;
            if (ww < 0 || ww >= WWD) continue;
            s += an[hh * WWD + ww];
        }
    }
    K[idx] = s * (1.0f / 9.0f);
}

// -------- 3:2 carry-save adder: sum-of-popcounts preserved as s + 2c ----------
__device__ __forceinline__ void csa(uint32_t a, uint32_t b, uint32_t c,
                                    uint32_t& s, uint32_t& cy)
{
    s  = a ^ b ^ c;                      // one LOP3
    cy = (a & b) | (c & (a | b));        // one LOP3 (majority)
}

// ================= binary conv: XNOR + CSA, planes + rolled tap loop ===========
// grid (NPIX/64, 4), block 256 = 8 warps; warp wy -> oc [ocb+8wy,+8), lane ->
// pixels (pix0+lane, pix0+32+lane).
// Activations staged in TWO uint4 smem PLANES indexed by padded pixel: lanes
// read consecutive 16B -> conflict-free LDS.128 (was 8-way conflicted).
// Tap loop is ROLLED (runtime offset) so the body (~6KB) fits the L0/L1.5 I$
// (fully unrolled was ~53KB). CSA 8->4 before POPC; weighted accumulate via
// integer multiplies so ptxas can steer them to IMAD (fma pipe).
template <bool FUSE_RES, bool STATS>
__global__ void __launch_bounds__(256)
binconv_kernel(const uint32_t* __restrict__ abits,
               const uint32_t* __restrict__ wbits,
               const int*      __restrict__ corr,
               const float*    __restrict__ alpha,
               const float*    __restrict__ Ksc,
               const float*    __restrict__ res,
               float*          __restrict__ out,
               float*          __restrict__ p1,
               float*          __restrict__ p2)
{
    __shared__ __align__(16) uint32_t ws[64 * 72];   // 18 KB weights
    __shared__ __align__(16) uint4 sp0[4 * PW];      // act words 0..3 per pixel
    __shared__ __align__(16) uint4 sp1[4 * PW];      // act words 4..7 per pixel
    __shared__ int   scorr[64 * 9];                  // 2.25 KB
    __shared__ float sal[64];

    const int tid    = threadIdx.x;
    const int ocbase = blockIdx.y * 64;
    const int pix0   = blockIdx.x * 64;
    const int n      = pix0 / HWH;               // 64 | 3136 -> one image/block
    const int pimg0  = pix0 - n * HWH;
    const int r0     = pimg0 / WWD;              // first unpadded row in block

    // ---- cooperative loads ----
    for (int i = tid; i < 64 * 72; i += 256) ws[i] = wbits[ocbase * 72 + i];
    {   // activation tile: padded rows r0..r0+3, transposed into 2 planes
        const uint4* src = (const uint4*)(abits + ((size_t)n * PIMG + r0 * PW) * 8);
        #pragma unroll
        for (int it = 0; it < 2; it++) {
            const int i = tid + it * 256;
            if (i < 4 * PW * 2) {
                const uint4 v = src[i];
                const int px = i >> 1;
                if (i & 1) sp1[px] = v; else sp0[px] = v;
            }
        }
    }
    for (int i = tid; i < 64 * 9; i += 256)  scorr[i] = corr[ocbase * 9 + i];
    if (tid < 64) sal[tid] = alpha[ocbase + tid];
    __syncthreads();

    const int lane = tid & 31;
    const int wy   = tid >> 5;
    const int pa = pimg0 + lane;
    const int pb = pa + 32;
    const int hA = pa / WWD, wA = pa - hA * WWD;
    const int hB = pb / WWD, wB = pb - hB * WWD;
    const float kvA = Ksc[pix0 + lane];
    const float kvB = Ksc[pix0 + 32 + lane];

    // plane index of pixel center: (h+1-r0)*PW + (w+1)
    const int tpA = (hA + 1 - r0) * PW + (wA + 1);
    const int tpB = (hB + 1 - r0) * PW + (wB + 1);

    int accA[8], accB[8];
    #pragma unroll
    for (int i = 0; i < 8; i++) { accA[i] = 0; accB[i] = 0; }

    const uint32_t* wsp = ws + (wy * 8) * 72;

    #pragma unroll 1
    for (int t = 0; t < 9; t++) {
        const int ty  = t / 3;
        const int off = (ty - 1) * PW + (t - 3 * ty) - 1;     // pixel offset
        const uint4 a0A = sp0[tpA + off];
        const uint4 a1A = sp1[tpA + off];
        const uint4 a0B = sp0[tpB + off];
        const uint4 a1B = sp1[tpB + off];
        const uint32_t* wt = wsp + t * 8;
        #pragma unroll
        for (int i = 0; i < 8; i++) {
            const uint4 w0 = *(const uint4*)(wt + i * 72);
            const uint4 w1 = *(const uint4*)(wt + i * 72 + 4);
            // ---- pixel A: 8 XOR -> CSA 8->4 -> 4 POPC ----
            {
                uint32_t x0 = a0A.x ^ w0.x, x1 = a0A.y ^ w0.y;
                uint32_t x2 = a0A.z ^ w0.z, x3 = a0A.w ^ w0.w;
                uint32_t x4 = a1A.x ^ w1.x, x5 = a1A.y ^ w1.y;
                uint32_t x6 = a1A.z ^ w1.z, x7 = a1A.w ^ w1.w;
                uint32_t s0, c0, s1, c1, s2, c2, sc, cc;
                csa(x0, x1, x2, s0, c0);
                csa(x3, x4, x5, s1, c1);
                csa(s0, s1, x6, s2, c2);
                csa(c0, c1, c2, sc, cc);
                accA[i] += (__popc(s2) + __popc(x7))
                         + __popc(sc) * 2 + __popc(cc) * 4;
            }
            // ---- pixel B ----
            {
                uint32_t x0 = a0B.x ^ w0.x, x1 = a0B.y ^ w0.y;
                uint32_t x2 = a0B.z ^ w0.z, x3 = a0B.w ^ w0.w;
                uint32_t x4 = a1B.x ^ w1.x, x5 = a1B.y ^ w1.y;
                uint32_t x6 = a1B.z ^ w1.z, x7 = a1B.w ^ w1.w;
                uint32_t s0, c0, s1, c1, s2, c2, sc, cc;
                csa(x0, x1, x2, s0, c0);
                csa(x3, x4, x5, s1, c1);
                csa(s0, s1, x6, s2, c2);
                csa(c0, c1, c2, sc, cc);
                accB[i] += (__popc(s2) + __popc(x7))
                         + __popc(sc) * 2 + __popc(cc) * 4;
            }
        }
    }

    // ---- boundary corrections (exact): remove guard-tap popc(w) terms ----
    const unsigned mA = (hA == 0 ? 0x007u : 0u) | (hA == HH - 1 ? 0x1C0u : 0u)
                      | (wA == 0 ? 0x049u : 0u) | (wA == WWD - 1 ? 0x124u : 0u);
    const unsigned mB = (hB == 0 ? 0x007u : 0u) | (hB == HH - 1 ? 0x1C0u : 0u)
                      | (wB == 0 ? 0x049u : 0u) | (wB == WWD - 1 ? 0x124u : 0u);
    int corA[8], corB[8];
    #pragma unroll
    for (int i = 0; i < 8; i++) { corA[i] = 0; corB[i] = 0; }
    if (mA | mB) {
        #pragma unroll 1
        for (int t = 0; t < 9; t++) {
            const int* cp = scorr + (wy * 8) * 9 + t;
            if ((mA >> t) & 1) {
                #pragma unroll
                for (int i = 0; i < 8; i++) corA[i] += cp[i * 9];
            }
            if ((mB >> t) & 1) {
                #pragma unroll
                for (int i = 0; i < 8; i++) corB[i] += cp[i * 9];
            }
        }
    }

    const size_t obaseA = (size_t)n * CC * HWH + pa;
    const size_t obaseB = (size_t)n * CC * HWH + pb;
    #pragma unroll
    for (int i = 0; i < 8; i++) {
        const int oc = ocbase + wy * 8 + i;
        const float al = sal[wy * 8 + i];
        float vA = al * kvA * (float)(KKT - 2 * accA[i] - corA[i]);
        float vB = al * kvB * (float)(KKT - 2 * accB[i] - corB[i]);
        const size_t iA = obaseA + (size_t)oc * HWH;
        const size_t iB = obaseB + (size_t)oc * HWH;
        if (FUSE_RES) { vA += res[iA]; vB += res[iB]; }
        vA = fmaxf(vA, 0.f);
        vB = fmaxf(vB, 0.f);
        out[iA] = vA;
        out[iB] = vB;
        if (STATS) {
            float sv = vA + vB;
            float sq = vA * vA + vB * vB;
            #pragma unroll
            for (int o = 16; o > 0; o >>= 1) {
                sv += __shfl_xor_sync(0xffffffffu, sv, o);
                sq += __shfl_xor_sync(0xffffffffu, sq, o);
            }
            if (lane == 0) {
                p1[(size_t)oc * GRIDX + blockIdx.x] = sv;
                p2[(size_t)oc * GRIDX + blockIdx.x] = sq;
            }
        }
    }
}

// ================================ launcher =====================================
extern "C" void kernel_launch(void* const* d_in, const int* in_sizes, int n_in,
                              void* d_out, int out_size)
{
    (void)in_sizes; (void)n_in; (void)out_size;
    const float* x  = (const float*)d_in[0];
    const float* g1 = (const float*)d_in[1];
    const float* b1 = (const float*)d_in[2];
    const float* w1 = (const float*)d_in[3];
    const float* g2 = (const float*)d_in[4];
    const float* b2 = (const float*)d_in[5];
    const float* w2 = (const float*)d_in[6];
    float* out = (float*)d_out;

    uint32_t *abits, *wbits;
    int *corr;
    float *alpha, *a, *K, *s1, *h1, *s2, *h2, *r, *p1, *p2;
    cudaGetSymbolAddress((void**)&abits, g_abits);
    cudaGetSymbolAddress((void**)&wbits, g_wbits);
    cudaGetSymbolAddress((void**)&corr,  g_corr);
    cudaGetSymbolAddress((void**)&alpha, g_alpha);
    cudaGetSymbolAddress((void**)&a,     g_a);
    cudaGetSymbolAddress((void**)&K,     g_K);
    cudaGetSymbolAddress((void**)&s1,    g_s1);
    cudaGetSymbolAddress((void**)&h1,    g_h1);
    cudaGetSymbolAddress((void**)&s2,    g_s2);
    cudaGetSymbolAddress((void**)&h2,    g_h2);
    cudaGetSymbolAddress((void**)&r,     g_r);
    cudaGetSymbolAddress((void**)&p1,    g_p1);
    cudaGetSymbolAddress((void**)&p2,    g_p2);

    const dim3 cgrid(GRIDX, 4);

    // ---- stage 1: BN1 -> pack -> K1 -> binary conv1 (+ReLU, +BN2 partials) ----
    bn_stats_kernel<<<CC, 512>>>(x, g1, b1, s1, h1);
    wprep_kernel<<<CC, 256>>>(w1, alpha, wbits, corr);
    bn_apply_pack_kernel<<<NPIX / 32, 256>>>(x, s1, h1, abits, a);
    box3_kernel<<<(NPIX + 255) / 256, 256>>>(a, K);
    binconv_kernel<false, true><<<cgrid, 256>>>(abits, wbits, corr, alpha, K, nullptr, r, p1, p2);

    // ---- stage 2: BN2(finalize) -> pack -> K2 -> conv2 + identity + ReLU ----
    bn2_finalize_kernel<<<CC, 256>>>(p1, p2, g2, b2, s2, h2);
    wprep_kernel<<<CC, 256>>>(w2, alpha, wbits, corr);
    bn_apply_pack_kernel<<<NPIX / 32, 256>>>(r, s2, h2, abits, a);
    box3_kernel<<<(NPIX + 255) / 256, 256>>>(a, K);
    binconv_kernel<true, false><<<cgrid, 256>>>(abits, wbits, corr, alpha, K, x, out, p1, p2);
}